// round 2
// baseline (speedup 1.0000x reference)
#include <cuda_runtime.h>
#include <math.h>

#define B_ 4
#define S_ 2048
#define D_ 1024
#define H_ 2048
#define E_ 8
#define NTOK (B_*S_)          /* 8192 */
#define NASSIGN (NTOK*2)      /* 16384 */
#define MU_F 0.7f
#define GAMMA_F 1.0f
#define LN_EPS_F 1e-5f

// ---------------- scratch (static __device__, no allocs) ----------------
__device__ float g_h [(size_t)NASSIGN * H_];   // 134 MB: relu(x@W1+b1) per assignment
__device__ float g_eo[(size_t)NASSIGN * D_];   //  67 MB: h@W2 per assignment
__device__ int   g_assign_tok[NASSIGN];
__device__ int   g_slot [NTOK * 2];
__device__ float g_wk   [NTOK * 2];
__device__ int   g_eidx [NTOK * 2];
__device__ int   g_counts [E_];
__device__ int   g_offsets[E_];
__device__ int   g_cursor [E_];

// ---------------- kernels ----------------
__global__ void zero_counts_kernel() {
    if (threadIdx.x < E_) g_counts[threadIdx.x] = 0;
}

// One warp per token: logits = x@Wg + bg, top-2, softmax weights.
__global__ void router_kernel(const float* __restrict__ x,
                              const float* __restrict__ Wg,
                              const float* __restrict__ bg) {
    int gwarp = (blockIdx.x * blockDim.x + threadIdx.x) >> 5;
    int lane  = threadIdx.x & 31;
    if (gwarp >= NTOK) return;
    const float* xr = x + (size_t)gwarp * D_;
    float acc[E_];
#pragma unroll
    for (int e = 0; e < E_; e++) acc[e] = 0.f;
    for (int d = lane; d < D_; d += 32) {
        float xv = xr[d];
        const float4* wr = reinterpret_cast<const float4*>(Wg + (size_t)d * E_);
        float4 w0 = wr[0], w1 = wr[1];
        acc[0] += xv * w0.x; acc[1] += xv * w0.y; acc[2] += xv * w0.z; acc[3] += xv * w0.w;
        acc[4] += xv * w1.x; acc[5] += xv * w1.y; acc[6] += xv * w1.z; acc[7] += xv * w1.w;
    }
#pragma unroll
    for (int e = 0; e < E_; e++) {
#pragma unroll
        for (int o = 16; o > 0; o >>= 1)
            acc[e] += __shfl_xor_sync(0xffffffffu, acc[e], o);
    }
    if (lane == 0) {
        float lg[E_];
#pragma unroll
        for (int e = 0; e < E_; e++) lg[e] = acc[e] + bg[e];
        int i0 = 0;
#pragma unroll
        for (int e = 1; e < E_; e++) if (lg[e] > lg[i0]) i0 = e;   // ties -> lowest idx (matches top_k)
        int i1 = -1;
#pragma unroll
        for (int e = 0; e < E_; e++) {
            if (e == i0) continue;
            if (i1 < 0 || lg[e] > lg[i1]) i1 = e;
        }
        float v0 = lg[i0], v1 = lg[i1];
        float e1 = __expf(v1 - v0);       // e0 = 1
        float inv = 1.f / (1.f + e1);
        g_eidx[gwarp*2]   = i0;  g_eidx[gwarp*2+1] = i1;
        g_wk  [gwarp*2]   = inv; g_wk  [gwarp*2+1] = e1 * inv;
        atomicAdd(&g_counts[i0], 1);
        atomicAdd(&g_counts[i1], 1);
    }
}

__global__ void offsets_kernel() {
    if (threadIdx.x == 0) {
        int acc = 0;
        for (int e = 0; e < E_; e++) {
            g_offsets[e] = acc;
            g_cursor[e]  = acc;
            acc += g_counts[e];
        }
    }
}

__global__ void scatter_kernel() {
    int t = blockIdx.x * blockDim.x + threadIdx.x;
    if (t >= NTOK) return;
#pragma unroll
    for (int k = 0; k < 2; k++) {
        int e = g_eidx[t*2 + k];
        int pos = atomicAdd(&g_cursor[e], 1);
        g_assign_tok[pos] = t;
        g_slot[t*2 + k] = pos;
    }
}

// Grouped SGEMM. PHASE1: A = x (param, gathered rows via g_assign_tok), C = g_h (device symbol).
//                !PHASE1: A = g_h (device symbol, direct rows),         C = g_eo (device symbol).
// IMPORTANT: scratch buffers are referenced ONLY inside device code (never passed
// as kernel args from host — host code sees the shadow symbol, not the device address).
// Tile 128x128, BK=8, 256 threads, 8x8 per-thread microtile.
template<int KD, int ND, bool RELU, bool PHASE1>
__global__ void __launch_bounds__(256, 2)
moe_gemm_kernel(const float* __restrict__ A_param, const float* __restrict__ W,
                const float* __restrict__ bias) {
    const float* A = PHASE1 ? A_param : (const float*)g_h;
    float*       C = PHASE1 ? (float*)g_h : (float*)g_eo;

    const int e   = blockIdx.z;
    const int cnt = g_counts[e];
    const int m0  = blockIdx.y * 128;
    if (m0 >= cnt) return;
    const int off = g_offsets[e];
    const int n0  = blockIdx.x * 128;
    const float* We = W + (size_t)e * KD * ND;

    __shared__ float As[8][128];
    __shared__ float Bs[8][128];

    const int tid = threadIdx.x;
    const int tx  = tid & 15;    // n
    const int ty  = tid >> 4;    // m

    // A-tile load mapping: each thread loads one float4 (row=tid>>1, kcol=(tid&1)*4)
    const int a_row = tid >> 1;
    const int a_k   = (tid & 1) * 4;
    const int gmrow = m0 + a_row;
    const bool avalid = (gmrow < cnt);
    const float* Arow = nullptr;
    if (avalid) {
        int r = PHASE1 ? g_assign_tok[off + gmrow] : (off + gmrow);
        Arow = A + (size_t)r * KD;
    }
    // B-tile load mapping: row kr=tid>>5 (0..7), cols (tid&31)*4
    const int b_kr = tid >> 5;
    const int b_nc = (tid & 31) * 4;
    const float* Bp = We + (size_t)b_kr * ND + n0 + b_nc;

    float cr[8][8];
#pragma unroll
    for (int i = 0; i < 8; i++)
#pragma unroll
        for (int j = 0; j < 8; j++) cr[i][j] = 0.f;

    for (int k0 = 0; k0 < KD; k0 += 8) {
        float4 av = make_float4(0.f, 0.f, 0.f, 0.f);
        if (avalid) av = *reinterpret_cast<const float4*>(Arow + k0 + a_k);
        float4 bv = *reinterpret_cast<const float4*>(Bp + (size_t)k0 * ND);
        __syncthreads();
        As[a_k+0][a_row] = av.x;
        As[a_k+1][a_row] = av.y;
        As[a_k+2][a_row] = av.z;
        As[a_k+3][a_row] = av.w;
        *reinterpret_cast<float4*>(&Bs[b_kr][b_nc]) = bv;
        __syncthreads();
#pragma unroll
        for (int kk = 0; kk < 8; kk++) {
            float a[8], b[8];
            *reinterpret_cast<float4*>(a)     = *reinterpret_cast<const float4*>(&As[kk][ty*8]);
            *reinterpret_cast<float4*>(a + 4) = *reinterpret_cast<const float4*>(&As[kk][ty*8 + 4]);
            *reinterpret_cast<float4*>(b)     = *reinterpret_cast<const float4*>(&Bs[kk][tx*8]);
            *reinterpret_cast<float4*>(b + 4) = *reinterpret_cast<const float4*>(&Bs[kk][tx*8 + 4]);
#pragma unroll
            for (int i = 0; i < 8; i++)
#pragma unroll
                for (int j = 0; j < 8; j++)
                    cr[i][j] = fmaf(a[i], b[j], cr[i][j]);
        }
    }

    const float* be = bias ? (bias + (size_t)e * ND) : nullptr;
#pragma unroll
    for (int i = 0; i < 8; i++) {
        int m = m0 + ty * 8 + i;
        if (m >= cnt) break;
        float* Crow = C + (size_t)(off + m) * ND + n0 + tx * 8;
#pragma unroll
        for (int j = 0; j < 8; j++) {
            float v = cr[i][j];
            if (be) v += be[n0 + tx * 8 + j];
            if (RELU) v = fmaxf(v, 0.f);
            Crow[j] = v;
        }
    }
}

// Combine top-2 expert outputs + bias + gate weights, momentum, residual, LayerNorm.
// One block per token, 256 threads, 4 elements each.
__global__ void combine_kernel(const float* __restrict__ x,
                               const float* __restrict__ momentum,
                               const float* __restrict__ b2,
                               const float* __restrict__ ln_g,
                               const float* __restrict__ ln_b,
                               float* __restrict__ out) {
    const int t   = blockIdx.x;
    const int tid = threadIdx.x;
    const int s0 = g_slot[t*2],     s1 = g_slot[t*2+1];
    const float w0 = g_wk[t*2],     w1 = g_wk[t*2+1];
    const int e0 = g_eidx[t*2],     e1 = g_eidx[t*2+1];
    const float* eo0 = g_eo + (size_t)s0 * D_;
    const float* eo1 = g_eo + (size_t)s1 * D_;
    const float* b20 = b2 + (size_t)e0 * D_;
    const float* b21 = b2 + (size_t)e1 * D_;
    const float* xr  = x        + (size_t)t * D_;
    const float* mr  = momentum + (size_t)t * D_;

    float ov[4], nmv[4];
    float sum = 0.f, sumsq = 0.f;
#pragma unroll
    for (int i = 0; i < 4; i++) {
        int d = tid + i * 256;
        float acc = w0 * (eo0[d] + b20[d]) + w1 * (eo1[d] + b21[d]);
        float nm  = -acc + MU_F * mr[d];
        float o   = xr[d] + GAMMA_F * nm;
        nmv[i] = nm; ov[i] = o;
        sum += o; sumsq += o * o;
    }
#pragma unroll
    for (int o = 16; o > 0; o >>= 1) {
        sum   += __shfl_xor_sync(0xffffffffu, sum,   o);
        sumsq += __shfl_xor_sync(0xffffffffu, sumsq, o);
    }
    __shared__ float red[16];
    const int warp = tid >> 5, lane = tid & 31;
    if (lane == 0) { red[warp] = sum; red[8 + warp] = sumsq; }
    __syncthreads();
    float tot = 0.f, totq = 0.f;
#pragma unroll
    for (int wgi = 0; wgi < 8; wgi++) { tot += red[wgi]; totq += red[8 + wgi]; }
    const float mean = tot * (1.f / D_);
    const float var  = totq * (1.f / D_) - mean * mean;
    const float inv  = rsqrtf(var + LN_EPS_F);

    float* out_ln = out;
    float* out_nm = out + (size_t)NTOK * D_;
#pragma unroll
    for (int i = 0; i < 4; i++) {
        int d = tid + i * 256;
        out_ln[(size_t)t * D_ + d] = (ov[i] - mean) * inv * ln_g[d] + ln_b[d];
        out_nm[(size_t)t * D_ + d] = nmv[i];
    }
}

// ---------------- launch ----------------
extern "C" void kernel_launch(void* const* d_in, const int* in_sizes, int n_in,
                              void* d_out, int out_size) {
    const float* x        = (const float*)d_in[0];
    const float* momentum = (const float*)d_in[1];
    const float* Wg       = (const float*)d_in[2];
    const float* bg       = (const float*)d_in[3];
    const float* W1       = (const float*)d_in[4];
    const float* b1       = (const float*)d_in[5];
    const float* W2       = (const float*)d_in[6];
    const float* b2       = (const float*)d_in[7];
    const float* ln_g     = (const float*)d_in[8];
    const float* ln_b     = (const float*)d_in[9];
    float* out            = (float*)d_out;

    zero_counts_kernel<<<1, 32>>>();
    router_kernel<<<NTOK / 8, 256>>>(x, Wg, bg);          // 8 warps/block
    offsets_kernel<<<1, 32>>>();
    scatter_kernel<<<NTOK / 256, 256>>>();

    {   // GEMM1: g_h = relu(x_gathered @ W1[e] + b1[e]),  K=D, N=H
        dim3 grid(H_ / 128, NTOK / 128, E_);
        moe_gemm_kernel<D_, H_, true, true><<<grid, 256>>>(x, W1, b1);
    }
    {   // GEMM2: g_eo = g_h @ W2[e],  K=H, N=D  (bias+gate applied in combine)
        dim3 grid(D_ / 128, NTOK / 128, E_);
        moe_gemm_kernel<H_, D_, false, false><<<grid, 256>>>(nullptr, W2, nullptr);
    }
    combine_kernel<<<NTOK, 256>>>(x, momentum, b2, ln_g, ln_b, out);
}

// round 6
// speedup vs baseline: 2.2955x; 2.2955x over previous
#include <cuda_runtime.h>
#include <cuda_bf16.h>
#include <math.h>
#include <stdint.h>

#define B_ 4
#define S_ 2048
#define D_ 1024
#define H_ 2048
#define E_ 8
#define NTOK (B_*S_)            /* 8192  */
#define NASSIGN (NTOK*2)        /* 16384 */
#define NPAD_MAX 17408          /* 16384 + 8*128 */
#define MU_F 0.7f
#define GAMMA_F 1.0f
#define LN_EPS_F 1e-5f

// ------------------------------------------------------------------
// scratch (static __device__; referenced ONLY from device code)
// ------------------------------------------------------------------
__device__ __align__(256) __nv_bfloat16 g_a1hi[(size_t)NPAD_MAX * D_];
__device__ __align__(256) __nv_bfloat16 g_a1lo[(size_t)NPAD_MAX * D_];
__device__ __align__(256) __nv_bfloat16 g_a2hi[(size_t)NPAD_MAX * H_];
__device__ __align__(256) __nv_bfloat16 g_a2lo[(size_t)NPAD_MAX * H_];
__device__ __align__(256) __nv_bfloat16 g_w1thi[(size_t)E_ * H_ * D_];   // [e][h][d]
__device__ __align__(256) __nv_bfloat16 g_w1tlo[(size_t)E_ * H_ * D_];
__device__ __align__(256) __nv_bfloat16 g_w2thi[(size_t)E_ * D_ * H_];   // [e][d][h]
__device__ __align__(256) __nv_bfloat16 g_w2tlo[(size_t)E_ * D_ * H_];
__device__ __align__(256) float g_eo[(size_t)NPAD_MAX * D_];
__device__ int   g_assign_tok[NPAD_MAX];
__device__ int   g_slot [NTOK * 2];
__device__ float g_wk   [NTOK * 2];
__device__ int   g_eidx [NTOK * 2];
__device__ int   g_counts [E_];
__device__ int   g_offsets_pad[E_];
__device__ int   g_cursor [E_];

// ------------------------------------------------------------------
// PTX helpers
// ------------------------------------------------------------------
__device__ __forceinline__ uint32_t smem_u32(const void* p) {
    uint32_t a;
    asm("{ .reg .u64 t; cvta.to.shared.u64 t, %1; cvt.u32.u64 %0, t; }" : "=r"(a) : "l"(p));
    return a;
}
#define CP_ASYNC16(dst, src) \
    asm volatile("cp.async.cg.shared.global [%0], [%1], 16;" :: "r"(dst), "l"(src) : "memory")
#define CP_COMMIT() asm volatile("cp.async.commit_group;" ::: "memory")
#define CP_WAIT1()  asm volatile("cp.async.wait_group 1;"  ::: "memory")
#define CP_WAIT0()  asm volatile("cp.async.wait_group 0;"  ::: "memory")

__device__ __forceinline__ void mma_bf16(float& c0, float& c1, float& c2, float& c3,
                                         uint32_t a0, uint32_t a1, uint32_t a2, uint32_t a3,
                                         uint32_t b0, uint32_t b1) {
    asm volatile("mma.sync.aligned.m16n8k16.row.col.f32.bf16.bf16.f32 "
                 "{%0,%1,%2,%3}, {%4,%5,%6,%7}, {%8,%9}, {%0,%1,%2,%3};"
                 : "+f"(c0), "+f"(c1), "+f"(c2), "+f"(c3)
                 : "r"(a0), "r"(a1), "r"(a2), "r"(a3), "r"(b0), "r"(b1));
}

// ------------------------------------------------------------------
// routing kernels
// ------------------------------------------------------------------
__global__ void init_kernel() {
    int i = blockIdx.x * blockDim.x + threadIdx.x;
    if (i < E_) g_counts[i] = 0;
    if (i < NPAD_MAX) g_assign_tok[i] = -1;
}

__global__ void router_kernel(const float* __restrict__ x,
                              const float* __restrict__ Wg,
                              const float* __restrict__ bg) {
    int gwarp = (blockIdx.x * blockDim.x + threadIdx.x) >> 5;
    int lane  = threadIdx.x & 31;
    if (gwarp >= NTOK) return;
    const float* xr = x + (size_t)gwarp * D_;
    float acc[E_];
#pragma unroll
    for (int e = 0; e < E_; e++) acc[e] = 0.f;
    for (int d = lane; d < D_; d += 32) {
        float xv = xr[d];
        const float4* wr = reinterpret_cast<const float4*>(Wg + (size_t)d * E_);
        float4 w0 = wr[0], w1 = wr[1];
        acc[0] += xv * w0.x; acc[1] += xv * w0.y; acc[2] += xv * w0.z; acc[3] += xv * w0.w;
        acc[4] += xv * w1.x; acc[5] += xv * w1.y; acc[6] += xv * w1.z; acc[7] += xv * w1.w;
    }
#pragma unroll
    for (int e = 0; e < E_; e++)
#pragma unroll
        for (int o = 16; o > 0; o >>= 1)
            acc[e] += __shfl_xor_sync(0xffffffffu, acc[e], o);
    if (lane == 0) {
        float lg[E_];
#pragma unroll
        for (int e = 0; e < E_; e++) lg[e] = acc[e] + bg[e];
        int i0 = 0;
#pragma unroll
        for (int e = 1; e < E_; e++) if (lg[e] > lg[i0]) i0 = e;
        int i1 = -1;
#pragma unroll
        for (int e = 0; e < E_; e++) {
            if (e == i0) continue;
            if (i1 < 0 || lg[e] > lg[i1]) i1 = e;
        }
        float e1 = __expf(lg[i1] - lg[i0]);
        float inv = 1.f / (1.f + e1);
        g_eidx[gwarp*2]   = i0;  g_eidx[gwarp*2+1] = i1;
        g_wk  [gwarp*2]   = inv; g_wk  [gwarp*2+1] = e1 * inv;
        atomicAdd(&g_counts[i0], 1);
        atomicAdd(&g_counts[i1], 1);
    }
}

__global__ void offsets_kernel() {
    if (threadIdx.x == 0) {
        int acc = 0;
        for (int e = 0; e < E_; e++) {
            g_offsets_pad[e] = acc;
            g_cursor[e]      = acc;
            acc += (g_counts[e] + 127) & ~127;
        }
    }
}

__global__ void scatter_kernel() {
    int t = blockIdx.x * blockDim.x + threadIdx.x;
    if (t >= NTOK) return;
#pragma unroll
    for (int k = 0; k < 2; k++) {
        int e = g_eidx[t*2 + k];
        int pos = atomicAdd(&g_cursor[e], 1);
        g_assign_tok[pos] = t;
        g_slot[t*2 + k] = pos;
    }
}

// gather x rows into padded, bf16-split A1 buffers (zeros for pad rows)
__global__ void gather_split_kernel(const float* __restrict__ x) {
    int slot = blockIdx.x;
    int t = g_assign_tok[slot];
    int d4 = threadIdx.x;                // 256 threads x 4 elems = 1024
    uint2 hp = make_uint2(0u, 0u), lp = make_uint2(0u, 0u);
    if (t >= 0) {
        float4 v = reinterpret_cast<const float4*>(x + (size_t)t * D_)[d4];
        float vv[4] = {v.x, v.y, v.z, v.w};
        unsigned short hb[4], lb[4];
#pragma unroll
        for (int i = 0; i < 4; i++) {
            __nv_bfloat16 h = __float2bfloat16(vv[i]);
            __nv_bfloat16 l = __float2bfloat16(vv[i] - __bfloat162float(h));
            hb[i] = __bfloat16_as_ushort(h);
            lb[i] = __bfloat16_as_ushort(l);
        }
        hp = make_uint2((uint32_t)hb[0] | ((uint32_t)hb[1] << 16),
                        (uint32_t)hb[2] | ((uint32_t)hb[3] << 16));
        lp = make_uint2((uint32_t)lb[0] | ((uint32_t)lb[1] << 16),
                        (uint32_t)lb[2] | ((uint32_t)lb[3] << 16));
    }
    reinterpret_cast<uint2*>(g_a1hi + (size_t)slot * D_)[d4] = hp;
    reinterpret_cast<uint2*>(g_a1lo + (size_t)slot * D_)[d4] = lp;
}

// transpose + bf16-split weights: in [e][RIN][CIN] -> out [e][CIN][RIN]
template<int RIN, int CIN, bool W1SEL>
__global__ void wsplit_transpose_kernel(const float* __restrict__ W) {
    __shared__ float tile[32][33];
    int e = blockIdx.z;
    int x0 = blockIdx.x * 32, y0 = blockIdx.y * 32;
    int tx = threadIdx.x, ty = threadIdx.y;  // 32 x 8
    const float* in = W + (size_t)e * RIN * CIN;
#pragma unroll
    for (int i = 0; i < 4; i++)
        tile[ty + i*8][tx] = in[(size_t)(y0 + ty + i*8) * CIN + x0 + tx];
    __syncthreads();
    __nv_bfloat16* oh = W1SEL ? g_w1thi : g_w2thi;
    __nv_bfloat16* ol = W1SEL ? g_w1tlo : g_w2tlo;
    size_t ob = (size_t)e * RIN * CIN;
#pragma unroll
    for (int i = 0; i < 4; i++) {
        float v = tile[tx][ty + i*8];
        __nv_bfloat16 h = __float2bfloat16(v);
        __nv_bfloat16 l = __float2bfloat16(v - __bfloat162float(h));
        size_t o = ob + (size_t)(x0 + ty + i*8) * RIN + (y0 + tx);
        oh[o] = h; ol[o] = l;
    }
}

// ------------------------------------------------------------------
// mma.sync bf16 grouped GEMM, 3-pass split (hi*hi + hi*lo + lo*hi).
// CTA tile 128x128, 8 warps (warp tile 64x32), BK=32, double-buffered cp.async.
// smem rows padded to 40 bf16 (80 B) -> conflict-free LDS.32 fragment loads.
// ------------------------------------------------------------------
#define RS 40                    /* padded row stride, bf16 elements */
#define HALF_SZ (128*RS*2)       /* 10240 B per operand-half */
#define STAGE_SZ (4*HALF_SZ)     /* 40960 B */
#define SMEM_TOTAL (2*STAGE_SZ)  /* 81920 B */

template<int KD, int ND, bool PHASE1>
__global__ void __launch_bounds__(256, 1)
moe_mma_kernel(const float* __restrict__ bias) {
    constexpr int NSLAB = KD / 32;
    const int e   = blockIdx.z;
    const int cnt = g_counts[e];
    const int m0  = blockIdx.y * 128;
    if (m0 >= cnt) return;
    const int off = g_offsets_pad[e];
    const int n0  = blockIdx.x * 128;

    const __nv_bfloat16* Ahi = PHASE1 ? g_a1hi  : g_a2hi;
    const __nv_bfloat16* Alo = PHASE1 ? g_a1lo  : g_a2lo;
    const __nv_bfloat16* Bhi = PHASE1 ? g_w1thi : g_w2thi;
    const __nv_bfloat16* Blo = PHASE1 ? g_w1tlo : g_w2tlo;

    extern __shared__ char smem[];
    const uint32_t sb = smem_u32(smem);
    const int tid  = threadIdx.x;
    const int wid  = tid >> 5;
    const int lane = tid & 31;
    const int lr   = lane >> 2;      // 0..7
    const int lc   = lane & 3;       // 0..3
    const int warp_m = (wid & 1) * 64;
    const int warp_n = (wid >> 1) * 32;

    const size_t arow = (size_t)(off + m0);
    const size_t brow = (size_t)e * ND + n0;

    // producer: 2048 16B-chunks per stage, 8 per thread
    const int p_kc = tid & 3;                  // k-chunk 0..3 (8 bf16 each)
    const int p_r0 = tid >> 2;                 // base row 0..63

    float acc[4][4][4];
#pragma unroll
    for (int mt = 0; mt < 4; mt++)
#pragma unroll
        for (int nt = 0; nt < 4; nt++)
#pragma unroll
            for (int c = 0; c < 4; c++) acc[mt][nt][c] = 0.f;

    auto load_stage = [&](int s) {
        const uint32_t stage = sb + (uint32_t)(s & 1) * STAGE_SZ;
        const int k0 = s * 32;
#pragma unroll
        for (int j = 0; j < 8; j++) {
            // chunk id = tid + j*256: op = (j>>1), rows split by (j&1)
            const int op = j >> 1;                       // 0:Ahi 1:Alo 2:Bhi 3:Blo
            const int r  = p_r0 + (j & 1) * 64;          // 0..127
            const __nv_bfloat16* base = (op == 0) ? Ahi : (op == 1) ? Alo
                                       : (op == 2) ? Bhi : Blo;
            const size_t grow = (op < 2) ? (arow + r) : (brow + r);
            const __nv_bfloat16* src = base + grow * KD + k0 + p_kc * 8;
            const uint32_t dst = stage + (uint32_t)op * HALF_SZ
                                 + (uint32_t)r * (RS * 2) + (uint32_t)p_kc * 16;
            CP_ASYNC16(dst, src);
        }
        CP_COMMIT();
    };

    load_stage(0);

    for (int s = 0; s < NSLAB; s++) {
        if (s + 1 < NSLAB) { load_stage(s + 1); CP_WAIT1(); }
        else               { CP_WAIT0(); }
        __syncthreads();

        const uint32_t stage = sb + (uint32_t)(s & 1) * STAGE_SZ;
        const uint32_t sAhi = stage;
        const uint32_t sAlo = stage + HALF_SZ;
        const uint32_t sBhi = stage + 2 * HALF_SZ;
        const uint32_t sBlo = stage + 3 * HALF_SZ;

#pragma unroll
        for (int kk = 0; kk < 2; kk++) {
            const int kel = kk * 16 + lc * 2;
            uint32_t bh[4][2], bl[4][2], af[4][4];
#pragma unroll
            for (int nt = 0; nt < 4; nt++) {
                const uint32_t boff = (uint32_t)((warp_n + nt*8 + lr) * RS + kel) * 2;
                bh[nt][0] = *(const uint32_t*)(smem + (sBhi + boff      - sb));
                bh[nt][1] = *(const uint32_t*)(smem + (sBhi + boff + 16 - sb));
                bl[nt][0] = *(const uint32_t*)(smem + (sBlo + boff      - sb));
                bl[nt][1] = *(const uint32_t*)(smem + (sBlo + boff + 16 - sb));
            }
#pragma unroll
            for (int mt = 0; mt < 4; mt++) {
                const uint32_t aoff = (uint32_t)((warp_m + mt*16 + lr) * RS + kel) * 2;
                af[mt][0] = *(const uint32_t*)(smem + (sAhi + aoff            - sb));
                af[mt][1] = *(const uint32_t*)(smem + (sAhi + aoff + 8*RS*2   - sb));
                af[mt][2] = *(const uint32_t*)(smem + (sAhi + aoff + 16       - sb));
                af[mt][3] = *(const uint32_t*)(smem + (sAhi + aoff + 8*RS*2+16 - sb));
            }
#pragma unroll
            for (int mt = 0; mt < 4; mt++)
#pragma unroll
                for (int nt = 0; nt < 4; nt++) {
                    mma_bf16(acc[mt][nt][0], acc[mt][nt][1], acc[mt][nt][2], acc[mt][nt][3],
                             af[mt][0], af[mt][1], af[mt][2], af[mt][3], bh[nt][0], bh[nt][1]);
                    mma_bf16(acc[mt][nt][0], acc[mt][nt][1], acc[mt][nt][2], acc[mt][nt][3],
                             af[mt][0], af[mt][1], af[mt][2], af[mt][3], bl[nt][0], bl[nt][1]);
                }
#pragma unroll
            for (int mt = 0; mt < 4; mt++) {
                const uint32_t aoff = (uint32_t)((warp_m + mt*16 + lr) * RS + kel) * 2;
                af[mt][0] = *(const uint32_t*)(smem + (sAlo + aoff            - sb));
                af[mt][1] = *(const uint32_t*)(smem + (sAlo + aoff + 8*RS*2   - sb));
                af[mt][2] = *(const uint32_t*)(smem + (sAlo + aoff + 16       - sb));
                af[mt][3] = *(const uint32_t*)(smem + (sAlo + aoff + 8*RS*2+16 - sb));
            }
#pragma unroll
            for (int mt = 0; mt < 4; mt++)
#pragma unroll
                for (int nt = 0; nt < 4; nt++)
                    mma_bf16(acc[mt][nt][0], acc[mt][nt][1], acc[mt][nt][2], acc[mt][nt][3],
                             af[mt][0], af[mt][1], af[mt][2], af[mt][3], bh[nt][0], bh[nt][1]);
        }
        __syncthreads();
    }

    // ---------------- epilogue (from registers) ----------------
#pragma unroll
    for (int mt = 0; mt < 4; mt++) {
        const size_t r0 = arow + warp_m + mt*16 + lr;
        const size_t r1 = r0 + 8;
#pragma unroll
        for (int nt = 0; nt < 4; nt++) {
            const int col = n0 + warp_n + nt*8 + lc*2;
            if (PHASE1) {
                const float bv0 = bias[(size_t)e * ND + col];
                const float bv1 = bias[(size_t)e * ND + col + 1];
#pragma unroll
                for (int half = 0; half < 2; half++) {
                    const size_t rr = half ? r1 : r0;
                    float v0 = acc[mt][nt][half*2]     + bv0;
                    float v1 = acc[mt][nt][half*2 + 1] + bv1;
                    v0 = fmaxf(v0, 0.f); v1 = fmaxf(v1, 0.f);
                    __nv_bfloat16 h0 = __float2bfloat16(v0);
                    __nv_bfloat16 h1 = __float2bfloat16(v1);
                    __nv_bfloat16 l0 = __float2bfloat16(v0 - __bfloat162float(h0));
                    __nv_bfloat16 l1 = __float2bfloat16(v1 - __bfloat162float(h1));
                    uint32_t hp = (uint32_t)__bfloat16_as_ushort(h0)
                                | ((uint32_t)__bfloat16_as_ushort(h1) << 16);
                    uint32_t lp = (uint32_t)__bfloat16_as_ushort(l0)
                                | ((uint32_t)__bfloat16_as_ushort(l1) << 16);
                    *reinterpret_cast<uint32_t*>(g_a2hi + rr * H_ + col) = hp;
                    *reinterpret_cast<uint32_t*>(g_a2lo + rr * H_ + col) = lp;
                }
            } else {
                *reinterpret_cast<float2*>(g_eo + r0 * D_ + col) =
                    make_float2(acc[mt][nt][0], acc[mt][nt][1]);
                *reinterpret_cast<float2*>(g_eo + r1 * D_ + col) =
                    make_float2(acc[mt][nt][2], acc[mt][nt][3]);
            }
        }
    }
}

// ------------------------------------------------------------------
// combine: eo(top2) + bias + gates -> momentum -> residual -> LayerNorm
// ------------------------------------------------------------------
__global__ void combine_kernel(const float* __restrict__ x,
                               const float* __restrict__ momentum,
                               const float* __restrict__ b2,
                               const float* __restrict__ ln_g,
                               const float* __restrict__ ln_b,
                               float* __restrict__ out) {
    const int t   = blockIdx.x;
    const int tid = threadIdx.x;
    const int s0 = g_slot[t*2],     s1 = g_slot[t*2+1];
    const float w0 = g_wk[t*2],     w1 = g_wk[t*2+1];
    const int e0 = g_eidx[t*2],     e1 = g_eidx[t*2+1];
    const float* eo0 = g_eo + (size_t)s0 * D_;
    const float* eo1 = g_eo + (size_t)s1 * D_;
    const float* b20 = b2 + (size_t)e0 * D_;
    const float* b21 = b2 + (size_t)e1 * D_;
    const float* xr  = x        + (size_t)t * D_;
    const float* mr  = momentum + (size_t)t * D_;

    float ov[4], nmv[4];
    float sum = 0.f, sumsq = 0.f;
#pragma unroll
    for (int i = 0; i < 4; i++) {
        int d = tid + i * 256;
        float acc = w0 * (eo0[d] + b20[d]) + w1 * (eo1[d] + b21[d]);
        float nm  = -acc + MU_F * mr[d];
        float o   = xr[d] + GAMMA_F * nm;
        nmv[i] = nm; ov[i] = o;
        sum += o; sumsq += o * o;
    }
#pragma unroll
    for (int o = 16; o > 0; o >>= 1) {
        sum   += __shfl_xor_sync(0xffffffffu, sum,   o);
        sumsq += __shfl_xor_sync(0xffffffffu, sumsq, o);
    }
    __shared__ float red[16];
    const int warp = tid >> 5, lane = tid & 31;
    if (lane == 0) { red[warp] = sum; red[8 + warp] = sumsq; }
    __syncthreads();
    float tot = 0.f, totq = 0.f;
#pragma unroll
    for (int wgi = 0; wgi < 8; wgi++) { tot += red[wgi]; totq += red[8 + wgi]; }
    const float mean = tot * (1.f / D_);
    const float var  = totq * (1.f / D_) - mean * mean;
    const float inv  = rsqrtf(var + LN_EPS_F);
#pragma unroll
    for (int i = 0; i < 4; i++) {
        int d = tid + i * 256;
        out[(size_t)t * D_ + d] = (ov[i] - mean) * inv * ln_g[d] + ln_b[d];
        out[(size_t)(NTOK + t) * D_ + d] = nmv[i];
    }
}

// ------------------------------------------------------------------
// launch
// ------------------------------------------------------------------
extern "C" void kernel_launch(void* const* d_in, const int* in_sizes, int n_in,
                              void* d_out, int out_size) {
    const float* x        = (const float*)d_in[0];
    const float* momentum = (const float*)d_in[1];
    const float* Wg       = (const float*)d_in[2];
    const float* bg       = (const float*)d_in[3];
    const float* W1       = (const float*)d_in[4];
    const float* b1       = (const float*)d_in[5];
    const float* W2       = (const float*)d_in[6];
    const float* b2       = (const float*)d_in[7];
    const float* ln_g     = (const float*)d_in[8];
    const float* ln_b     = (const float*)d_in[9];
    float* out            = (float*)d_out;

    cudaFuncSetAttribute(moe_mma_kernel<D_, H_, true>,
                         cudaFuncAttributeMaxDynamicSharedMemorySize, SMEM_TOTAL);
    cudaFuncSetAttribute(moe_mma_kernel<H_, D_, false>,
                         cudaFuncAttributeMaxDynamicSharedMemorySize, SMEM_TOTAL);

    init_kernel<<<(NPAD_MAX + 255) / 256, 256>>>();
    router_kernel<<<NTOK / 8, 256>>>(x, Wg, bg);
    offsets_kernel<<<1, 32>>>();
    scatter_kernel<<<NTOK / 256, 256>>>();
    gather_split_kernel<<<NPAD_MAX, 256>>>(x);

    {   // W1 [e][1024][2048] -> W1t [e][2048][1024]
        dim3 grid(H_ / 32, D_ / 32, E_);
        wsplit_transpose_kernel<D_, H_, true><<<grid, dim3(32, 8)>>>(W1);
    }
    {   // W2 [e][2048][1024] -> W2t [e][1024][2048]
        dim3 grid(D_ / 32, H_ / 32, E_);
        wsplit_transpose_kernel<H_, D_, false><<<grid, dim3(32, 8)>>>(W2);
    }

    {   // GEMM1: A1 @ W1t -> relu+bias -> split -> A2
        dim3 grid(H_ / 128, 64, E_);
        moe_mma_kernel<D_, H_, true><<<grid, 256, SMEM_TOTAL>>>(b1);
    }
    {   // GEMM2: A2 @ W2t -> g_eo (fp32)
        dim3 grid(D_ / 128, 64, E_);
        moe_mma_kernel<H_, D_, false><<<grid, 256, SMEM_TOTAL>>>(nullptr);
    }

    combine_kernel<<<NTOK, 256>>>(x, momentum, b2, ln_g, ln_b, out);
}

// round 8
// speedup vs baseline: 7.2368x; 3.1526x over previous
#include <cuda_runtime.h>
#include <cuda_fp16.h>
#include <math.h>
#include <stdint.h>

#define B_ 4
#define S_ 2048
#define D_ 1024
#define H_ 2048
#define E_ 8
#define NTOK (B_*S_)            /* 8192  */
#define NPAD_MAX 17408          /* 16384 + 8*128 */
#define MTILES (NPAD_MAX/128)   /* 136 */
#define MU_F 0.7f
#define GAMMA_F 1.0f
#define LN_EPS_F 1e-5f

// ------------------------------------------------------------------
// scratch (static __device__; referenced ONLY from device code)
// ------------------------------------------------------------------
__device__ __align__(256) __half g_a1 [(size_t)NPAD_MAX * D_];
__device__ __align__(256) __half g_a2 [(size_t)NPAD_MAX * H_];
__device__ __align__(256) __half g_w1t[(size_t)E_ * H_ * D_];   // [e][h][d]
__device__ __align__(256) __half g_w2t[(size_t)E_ * D_ * H_];   // [e][d][h]
__device__ __align__(256) float  g_eo [(size_t)NPAD_MAX * D_];
__device__ int   g_assign_tok[NPAD_MAX];
__device__ int   g_slot [NTOK * 2];
__device__ float g_wk   [NTOK * 2];
__device__ int   g_eidx [NTOK * 2];
__device__ int   g_counts [E_];
__device__ int   g_offsets_pad[E_];
__device__ int   g_cursor [E_];

// ------------------------------------------------------------------
// PTX helpers
// ------------------------------------------------------------------
__device__ __forceinline__ uint32_t smem_u32(const void* p) {
    uint32_t a;
    asm("{ .reg .u64 t; cvta.to.shared.u64 t, %1; cvt.u32.u64 %0, t; }" : "=r"(a) : "l"(p));
    return a;
}
#define CP_ASYNC16(dst, src) \
    asm volatile("cp.async.cg.shared.global [%0], [%1], 16;" :: "r"(dst), "l"(src) : "memory")
#define CP_COMMIT() asm volatile("cp.async.commit_group;" ::: "memory")
#define CP_WAIT1()  asm volatile("cp.async.wait_group 1;"  ::: "memory")
#define CP_WAIT0()  asm volatile("cp.async.wait_group 0;"  ::: "memory")

#define LDSM4(r0, r1, r2, r3, addr) \
    asm volatile("ldmatrix.sync.aligned.m8n8.x4.shared.b16 {%0,%1,%2,%3}, [%4];" \
                 : "=r"(r0), "=r"(r1), "=r"(r2), "=r"(r3) : "r"(addr))

__device__ __forceinline__ void mma_f16(float& c0, float& c1, float& c2, float& c3,
                                        uint32_t a0, uint32_t a1, uint32_t a2, uint32_t a3,
                                        uint32_t b0, uint32_t b1) {
    asm volatile("mma.sync.aligned.m16n8k16.row.col.f32.f16.f16.f32 "
                 "{%0,%1,%2,%3}, {%4,%5,%6,%7}, {%8,%9}, {%0,%1,%2,%3};"
                 : "+f"(c0), "+f"(c1), "+f"(c2), "+f"(c3)
                 : "r"(a0), "r"(a1), "r"(a2), "r"(a3), "r"(b0), "r"(b1));
}

// ------------------------------------------------------------------
// routing kernels
// ------------------------------------------------------------------
__global__ void init_kernel() {
    int i = blockIdx.x * blockDim.x + threadIdx.x;
    if (i < E_) g_counts[i] = 0;
    if (i < NPAD_MAX) g_assign_tok[i] = -1;
}

__global__ void router_kernel(const float* __restrict__ x,
                              const float* __restrict__ Wg,
                              const float* __restrict__ bg) {
    int gwarp = (blockIdx.x * blockDim.x + threadIdx.x) >> 5;
    int lane  = threadIdx.x & 31;
    if (gwarp >= NTOK) return;
    const float* xr = x + (size_t)gwarp * D_;
    float acc[E_];
#pragma unroll
    for (int e = 0; e < E_; e++) acc[e] = 0.f;
    for (int d = lane; d < D_; d += 32) {
        float xv = xr[d];
        const float4* wr = reinterpret_cast<const float4*>(Wg + (size_t)d * E_);
        float4 w0 = wr[0], w1 = wr[1];
        acc[0] += xv * w0.x; acc[1] += xv * w0.y; acc[2] += xv * w0.z; acc[3] += xv * w0.w;
        acc[4] += xv * w1.x; acc[5] += xv * w1.y; acc[6] += xv * w1.z; acc[7] += xv * w1.w;
    }
#pragma unroll
    for (int e = 0; e < E_; e++)
#pragma unroll
        for (int o = 16; o > 0; o >>= 1)
            acc[e] += __shfl_xor_sync(0xffffffffu, acc[e], o);
    if (lane == 0) {
        float lg[E_];
#pragma unroll
        for (int e = 0; e < E_; e++) lg[e] = acc[e] + bg[e];
        int i0 = 0;
#pragma unroll
        for (int e = 1; e < E_; e++) if (lg[e] > lg[i0]) i0 = e;
        int i1 = -1;
#pragma unroll
        for (int e = 0; e < E_; e++) {
            if (e == i0) continue;
            if (i1 < 0 || lg[e] > lg[i1]) i1 = e;
        }
        float e1 = __expf(lg[i1] - lg[i0]);
        float inv = 1.f / (1.f + e1);
        g_eidx[gwarp*2]   = i0;  g_eidx[gwarp*2+1] = i1;
        g_wk  [gwarp*2]   = inv; g_wk  [gwarp*2+1] = e1 * inv;
        atomicAdd(&g_counts[i0], 1);
        atomicAdd(&g_counts[i1], 1);
    }
}

__global__ void offsets_kernel() {
    if (threadIdx.x == 0) {
        int acc = 0;
        for (int e = 0; e < E_; e++) {
            g_offsets_pad[e] = acc;
            g_cursor[e]      = acc;
            acc += (g_counts[e] + 127) & ~127;
        }
    }
}

__global__ void scatter_kernel() {
    int t = blockIdx.x * blockDim.x + threadIdx.x;
    if (t >= NTOK) return;
#pragma unroll
    for (int k = 0; k < 2; k++) {
        int e = g_eidx[t*2 + k];
        int pos = atomicAdd(&g_cursor[e], 1);
        g_assign_tok[pos] = t;
        g_slot[t*2 + k] = pos;
    }
}

// gather x rows into padded fp16 A1 (zeros for pad rows)
__global__ void gather_half_kernel(const float* __restrict__ x) {
    int slot = blockIdx.x;
    int t = g_assign_tok[slot];
    int d4 = threadIdx.x;                // 256 threads x 4 elems = 1024
    uint2 pk = make_uint2(0u, 0u);
    if (t >= 0) {
        float4 v = reinterpret_cast<const float4*>(x + (size_t)t * D_)[d4];
        __half2 p0 = __floats2half2_rn(v.x, v.y);
        __half2 p1 = __floats2half2_rn(v.z, v.w);
        pk.x = *reinterpret_cast<uint32_t*>(&p0);
        pk.y = *reinterpret_cast<uint32_t*>(&p1);
    }
    reinterpret_cast<uint2*>(g_a1 + (size_t)slot * D_)[d4] = pk;
}

// transpose + fp16 weights: in [e][RIN][CIN] -> out [e][CIN][RIN]
template<int RIN, int CIN, bool W1SEL>
__global__ void wtrans_half_kernel(const float* __restrict__ W) {
    __shared__ float tile[32][33];
    int e = blockIdx.z;
    int x0 = blockIdx.x * 32, y0 = blockIdx.y * 32;
    int tx = threadIdx.x, ty = threadIdx.y;  // 32 x 8
    const float* in = W + (size_t)e * RIN * CIN;
#pragma unroll
    for (int i = 0; i < 4; i++)
        tile[ty + i*8][tx] = in[(size_t)(y0 + ty + i*8) * CIN + x0 + tx];
    __syncthreads();
    __half* ot = W1SEL ? g_w1t : g_w2t;
    size_t ob = (size_t)e * RIN * CIN;
#pragma unroll
    for (int i = 0; i < 4; i++) {
        float v = tile[tx][ty + i*8];
        size_t o = ob + (size_t)(x0 + ty + i*8) * RIN + (y0 + tx);
        ot[o] = __float2half_rn(v);
    }
}

// ------------------------------------------------------------------
// fp16 mma.sync grouped GEMM: CTA 128x128, 8 warps (64x32), BK=64,
// XOR-swizzled 128B smem rows, ldmatrix.x4 fragments, 2-stage cp.async.
// ------------------------------------------------------------------
#define STAGE_SZ 32768           /* A 16KB + B 16KB */
#define SMEM_TOTAL (2*STAGE_SZ)  /* 65536 */

template<int KD, int ND, bool PHASE1>
__global__ void __launch_bounds__(256)
moe_mma_kernel(const float* __restrict__ bias) {
    constexpr int NSLAB = KD / 64;
    const int e   = blockIdx.z;
    const int cnt = g_counts[e];
    const int m0  = blockIdx.y * 128;
    if (m0 >= cnt) return;
    const int off = g_offsets_pad[e];
    const int n0  = blockIdx.x * 128;

    const __half* A = PHASE1 ? g_a1  : g_a2;
    const __half* Bw = PHASE1 ? g_w1t : g_w2t;

    extern __shared__ char smem[];
    const uint32_t sb = smem_u32(smem);
    const int tid  = threadIdx.x;
    const int wid  = tid >> 5;
    const int lane = tid & 31;
    const int lr   = lane >> 2;      // 0..7
    const int lc   = lane & 3;       // 0..3
    const int warp_m = (wid & 1) * 64;
    const int warp_n = (wid >> 1) * 32;

    const size_t arow = (size_t)(off + m0);
    const size_t brow = (size_t)e * ND + n0;

    // producer mapping: 2048 chunks/stage (A 1024 + B 1024), 8 per thread
    float acc[4][4][4];
#pragma unroll
    for (int mt = 0; mt < 4; mt++)
#pragma unroll
        for (int nt = 0; nt < 4; nt++)
#pragma unroll
            for (int c = 0; c < 4; c++) acc[mt][nt][c] = 0.f;

    auto load_stage = [&](int s) {
        const uint32_t stage = sb + (uint32_t)(s & 1) * STAGE_SZ;
        const int k0 = s * 64;
#pragma unroll
        for (int j = 0; j < 8; j++) {
            const int cid = tid + j * 256;          // 0..2047
            const int op  = cid >> 10;              // 0:A 1:B
            const int loc = cid & 1023;
            const int r   = loc >> 3;               // 0..127
            const int c   = loc & 7;                // 16B chunk within 128B row
            const __half* src = (op == 0)
                ? (A  + (arow + r) * KD + k0 + c * 8)
                : (Bw + (brow + r) * KD + k0 + c * 8);
            const uint32_t dst = stage + (uint32_t)op * 16384u
                               + (uint32_t)r * 128u + (uint32_t)((c ^ (r & 7)) << 4);
            CP_ASYNC16(dst, src);
        }
        CP_COMMIT();
    };

    load_stage(0);

    // ldmatrix lane-address components (constant across slabs)
    const int a_row_l = warp_m + (lane & 7) + ((lane >> 3) & 1) * 8;  // + mt*16
    const int a_kh    = lane >> 4;                                     // 0/1
    const int b_m     = lane >> 3;                                     // 0..3
    const int b_nt_l  = b_m >> 1;                                      // 0/1 (+p*2)
    const int b_kh    = b_m & 1;
    const int b_row_l = warp_n + (lane & 7) + b_nt_l * 8;              // + p*16

    for (int s = 0; s < NSLAB; s++) {
        if (s + 1 < NSLAB) { load_stage(s + 1); CP_WAIT1(); }
        else               { CP_WAIT0(); }
        __syncthreads();

        const uint32_t stage = sb + (uint32_t)(s & 1) * STAGE_SZ;
        const uint32_t sA = stage;
        const uint32_t sB = stage + 16384u;

#pragma unroll
        for (int ks = 0; ks < 4; ks++) {
            uint32_t a[4][4], b[8];
            // B fragments: 2 x ldmatrix.x4 -> 4 n-tiles x (b0,b1)
#pragma unroll
            for (int p = 0; p < 2; p++) {
                const int nrow = b_row_l + p * 16;
                const int kch  = ks * 2 + b_kh;
                const uint32_t addr = sB + (uint32_t)nrow * 128u
                                    + (uint32_t)((kch ^ (nrow & 7)) << 4);
                LDSM4(b[p*4+0], b[p*4+1], b[p*4+2], b[p*4+3], addr);
            }
            // A fragments: 4 x ldmatrix.x4
#pragma unroll
            for (int mt = 0; mt < 4; mt++) {
                const int mrow = a_row_l + mt * 16;
                const int kch  = ks * 2 + a_kh;
                const uint32_t addr = sA + (uint32_t)mrow * 128u
                                    + (uint32_t)((kch ^ (mrow & 7)) << 4);
                LDSM4(a[mt][0], a[mt][1], a[mt][2], a[mt][3], addr);
            }
#pragma unroll
            for (int mt = 0; mt < 4; mt++)
#pragma unroll
                for (int nt = 0; nt < 4; nt++)
                    mma_f16(acc[mt][nt][0], acc[mt][nt][1], acc[mt][nt][2], acc[mt][nt][3],
                            a[mt][0], a[mt][1], a[mt][2], a[mt][3],
                            b[nt*2], b[nt*2+1]);
        }
        __syncthreads();
    }

    // ---------------- epilogue (from registers) ----------------
#pragma unroll
    for (int mt = 0; mt < 4; mt++) {
        const size_t r0 = arow + warp_m + mt*16 + lr;
        const size_t r1 = r0 + 8;
#pragma unroll
        for (int nt = 0; nt < 4; nt++) {
            const int col = n0 + warp_n + nt*8 + lc*2;
            if (PHASE1) {
                const float bv0 = bias[(size_t)e * ND + col];
                const float bv1 = bias[(size_t)e * ND + col + 1];
                float v0 = fmaxf(acc[mt][nt][0] + bv0, 0.f);
                float v1 = fmaxf(acc[mt][nt][1] + bv1, 0.f);
                float v2 = fmaxf(acc[mt][nt][2] + bv0, 0.f);
                float v3 = fmaxf(acc[mt][nt][3] + bv1, 0.f);
                __half2 p0 = __floats2half2_rn(v0, v1);
                __half2 p1 = __floats2half2_rn(v2, v3);
                *reinterpret_cast<__half2*>(g_a2 + r0 * H_ + col) = p0;
                *reinterpret_cast<__half2*>(g_a2 + r1 * H_ + col) = p1;
            } else {
                *reinterpret_cast<float2*>(g_eo + r0 * D_ + col) =
                    make_float2(acc[mt][nt][0], acc[mt][nt][1]);
                *reinterpret_cast<float2*>(g_eo + r1 * D_ + col) =
                    make_float2(acc[mt][nt][2], acc[mt][nt][3]);
            }
        }
    }
}

// ------------------------------------------------------------------
// combine: eo(top2) + bias + gates -> momentum -> residual -> LayerNorm
// ------------------------------------------------------------------
__global__ void combine_kernel(const float* __restrict__ x,
                               const float* __restrict__ momentum,
                               const float* __restrict__ b2,
                               const float* __restrict__ ln_g,
                               const float* __restrict__ ln_b,
                               float* __restrict__ out) {
    const int t   = blockIdx.x;
    const int tid = threadIdx.x;
    const int s0 = g_slot[t*2],     s1 = g_slot[t*2+1];
    const float w0 = g_wk[t*2],     w1 = g_wk[t*2+1];
    const int e0 = g_eidx[t*2],     e1 = g_eidx[t*2+1];
    const float* eo0 = g_eo + (size_t)s0 * D_;
    const float* eo1 = g_eo + (size_t)s1 * D_;
    const float* b20 = b2 + (size_t)e0 * D_;
    const float* b21 = b2 + (size_t)e1 * D_;
    const float* xr  = x        + (size_t)t * D_;
    const float* mr  = momentum + (size_t)t * D_;

    float ov[4], nmv[4];
    float sum = 0.f, sumsq = 0.f;
#pragma unroll
    for (int i = 0; i < 4; i++) {
        int d = tid + i * 256;
        float acc = w0 * (eo0[d] + b20[d]) + w1 * (eo1[d] + b21[d]);
        float nm  = -acc + MU_F * mr[d];
        float o   = xr[d] + GAMMA_F * nm;
        nmv[i] = nm; ov[i] = o;
        sum += o; sumsq += o * o;
    }
#pragma unroll
    for (int o = 16; o > 0; o >>= 1) {
        sum   += __shfl_xor_sync(0xffffffffu, sum,   o);
        sumsq += __shfl_xor_sync(0xffffffffu, sumsq, o);
    }
    __shared__ float red[16];
    const int warp = tid >> 5, lane = tid & 31;
    if (lane == 0) { red[warp] = sum; red[8 + warp] = sumsq; }
    __syncthreads();
    float tot = 0.f, totq = 0.f;
#pragma unroll
    for (int wgi = 0; wgi < 8; wgi++) { tot += red[wgi]; totq += red[8 + wgi]; }
    const float mean = tot * (1.f / D_);
    const float var  = totq * (1.f / D_) - mean * mean;
    const float inv  = rsqrtf(var + LN_EPS_F);
#pragma unroll
    for (int i = 0; i < 4; i++) {
        int d = tid + i * 256;
        out[(size_t)t * D_ + d] = (ov[i] - mean) * inv * ln_g[d] + ln_b[d];
        out[(size_t)(NTOK + t) * D_ + d] = nmv[i];
    }
}

// ------------------------------------------------------------------
// launch
// ------------------------------------------------------------------
extern "C" void kernel_launch(void* const* d_in, const int* in_sizes, int n_in,
                              void* d_out, int out_size) {
    const float* x        = (const float*)d_in[0];
    const float* momentum = (const float*)d_in[1];
    const float* Wg       = (const float*)d_in[2];
    const float* bg       = (const float*)d_in[3];
    const float* W1       = (const float*)d_in[4];
    const float* b1       = (const float*)d_in[5];
    const float* W2       = (const float*)d_in[6];
    const float* b2       = (const float*)d_in[7];
    const float* ln_g     = (const float*)d_in[8];
    const float* ln_b     = (const float*)d_in[9];
    float* out            = (float*)d_out;

    cudaFuncSetAttribute(moe_mma_kernel<D_, H_, true>,
                         cudaFuncAttributeMaxDynamicSharedMemorySize, SMEM_TOTAL);
    cudaFuncSetAttribute(moe_mma_kernel<H_, D_, false>,
                         cudaFuncAttributeMaxDynamicSharedMemorySize, SMEM_TOTAL);

    init_kernel<<<(NPAD_MAX + 255) / 256, 256>>>();
    router_kernel<<<NTOK / 8, 256>>>(x, Wg, bg);
    offsets_kernel<<<1, 32>>>();
    scatter_kernel<<<NTOK / 256, 256>>>();
    gather_half_kernel<<<NPAD_MAX, 256>>>(x);

    {   // W1 [e][1024][2048] -> W1t [e][2048][1024] fp16
        dim3 grid(H_ / 32, D_ / 32, E_);
        wtrans_half_kernel<D_, H_, true><<<grid, dim3(32, 8)>>>(W1);
    }
    {   // W2 [e][2048][1024] -> W2t [e][1024][2048] fp16
        dim3 grid(D_ / 32, H_ / 32, E_);
        wtrans_half_kernel<H_, D_, false><<<grid, dim3(32, 8)>>>(W2);
    }

    {   // GEMM1: A1 @ W1t -> relu+bias -> fp16 -> A2
        dim3 grid(H_ / 128, MTILES, E_);
        moe_mma_kernel<D_, H_, true><<<grid, 256, SMEM_TOTAL>>>(b1);
    }
    {   // GEMM2: A2 @ W2t -> g_eo (fp32)
        dim3 grid(D_ / 128, MTILES, E_);
        moe_mma_kernel<H_, D_, false><<<grid, 256, SMEM_TOTAL>>>(nullptr);
    }

    combine_kernel<<<NTOK, 256>>>(x, momentum, b2, ln_g, ln_b, out);
}